// round 3
// baseline (speedup 1.0000x reference)
#include <cuda_runtime.h>
#include <cstdint>

// Problem constants: points (B=4, C=84, H=512, W=512) fp32.
// probs = max over channels [0,80); 3x3 NMS with zero padding;
// out = points * mask (mask broadcast over all 84 channels).
#define B_  4
#define C_  84
#define CP_ 80           // channels participating in the max
#define H_  512
#define W_  512
#define HW_ (H_ * W_)    // 262144
#define HW4_ (HW_ / 4)   // 65536 float4 per (b) image plane

// Scratch (allocation-guard-safe __device__ globals): 4 MB each.
__device__ static float g_probs[B_ * HW_];
__device__ static float g_mask [B_ * HW_];

// ---------------------------------------------------------------------------
// Kernel 1: per-pixel channel max over c in [0, 80).  float4 along W.
// One thread = 4 pixels. Reads 80 strided float4, writes one float4.
// ---------------------------------------------------------------------------
__global__ __launch_bounds__(256)
void k_probs(const float* __restrict__ pts) {
    int t = blockIdx.x * blockDim.x + threadIdx.x;   // 0 .. B_*HW4_-1 = 262143
    int b   = t >> 16;                               // HW4_ = 65536 = 2^16
    int rem = t & (HW4_ - 1);
    const float4* src = reinterpret_cast<const float4*>(pts)
                        + (long)b * (C_ * HW4_) + rem;
    float4 m = src[0];
    #pragma unroll 10
    for (int c = 1; c < CP_; ++c) {
        float4 v = src[(long)c * HW4_];
        m.x = fmaxf(m.x, v.x);
        m.y = fmaxf(m.y, v.y);
        m.z = fmaxf(m.z, v.z);
        m.w = fmaxf(m.w, v.w);
    }
    reinterpret_cast<float4*>(g_probs)[t] = m;
}

// ---------------------------------------------------------------------------
// Kernel 2: 3x3 NMS mask. Scalar per pixel; everything L2/L1-resident (4 MB).
// Raster-earlier neighbors use strict >, later use >=. OOB neighbor = 0.0f
// (matches jnp.pad zero semantics — negative border peaks get suppressed).
// ---------------------------------------------------------------------------
__device__ __forceinline__ float nb_probs(int b, int h, int w) {
    if (h < 0 || h >= H_ || w < 0 || w >= W_) return 0.0f;
    return g_probs[(b << 18) + (h << 9) + w];
}

__global__ __launch_bounds__(256)
void k_mask() {
    int idx = blockIdx.x * blockDim.x + threadIdx.x; // 0 .. B_*HW_-1
    int b   = idx >> 18;                             // HW_ = 2^18
    int pix = idx & (HW_ - 1);
    int h   = pix >> 9;
    int w   = pix & (W_ - 1);
    float p = g_probs[idx];
    bool ok =
        (p >  nb_probs(b, h - 1, w - 1)) &&
        (p >  nb_probs(b, h - 1, w    )) &&
        (p >  nb_probs(b, h - 1, w + 1)) &&
        (p >  nb_probs(b, h,     w - 1)) &&
        (p >= nb_probs(b, h,     w + 1)) &&
        (p >= nb_probs(b, h + 1, w - 1)) &&
        (p >= nb_probs(b, h + 1, w    )) &&
        (p >= nb_probs(b, h + 1, w + 1));
    g_mask[idx] = ok ? 1.0f : 0.0f;
}

// ---------------------------------------------------------------------------
// Kernel 3: out = points * mask[b, pix], streaming float4.
// g indexes float4 over the whole tensor: 22,020,096 threads.
// pix4 = g mod HW4_ (valid since HW4_ divides the per-batch float4 count).
// ---------------------------------------------------------------------------
__global__ __launch_bounds__(256)
void k_mul(const float* __restrict__ pts, float* __restrict__ out) {
    unsigned g = blockIdx.x * blockDim.x + threadIdx.x;  // < 22,020,096
    const unsigned PER_B = (unsigned)C_ * HW4_;          // 5,505,024
    unsigned b    = g / PER_B;                            // const-div -> mul
    unsigned pix4 = g & (HW4_ - 1);
    float4 v = reinterpret_cast<const float4*>(pts)[g];
    float4 m = reinterpret_cast<const float4*>(g_mask)[b * HW4_ + pix4];
    v.x *= m.x; v.y *= m.y; v.z *= m.z; v.w *= m.w;
    reinterpret_cast<float4*>(out)[g] = v;
}

// ---------------------------------------------------------------------------
extern "C" void kernel_launch(void* const* d_in, const int* in_sizes, int n_in,
                              void* d_out, int out_size) {
    const float* pts = (const float*)d_in[0];
    float*       out = (float*)d_out;

    // K1: B_*HW4_ = 262144 threads
    k_probs<<<(B_ * HW4_) / 256, 256>>>(pts);
    // K2: B_*HW_ = 4,194,304 threads
    k_mask<<<(B_ * HW_) / 256, 256>>>();
    // K3: total float4 = B_*C_*HW4_ = 22,020,096 threads
    k_mul<<<(B_ * C_ * HW4_) / 256, 256>>>(pts, out);
}